// round 3
// baseline (speedup 1.0000x reference)
#include <cuda_runtime.h>
#include <cuda_bf16.h>
#include <cstdint>

// ---------------------------------------------------------------------------
// LSTM cell: h_new = tanh(c*sigm(zf) + sigm(zi)*tanh(zp)) * sigm(zs)
// z_g = [x,h] @ W_g + b_g     B=4096, IN=H=1024, K=2048
//
// Harness compiles PTX at compute_100 (no 'a' suffix) => tcgen05 unavailable.
// Portable mma.sync.m16n8k8.tf32 with rna-prerounded operands,
// cp.async 4-stage pipeline, XOR-swizzled smem.
// ---------------------------------------------------------------------------

#define B_DIM 4096
#define H_DIM 1024
#define K_DIM 2048
#define N_ALL 4096          // 4 gates x 1024

// Scratch (__device__ globals are the sanctioned scratch mechanism)
__device__ float g_hx[(size_t)B_DIM * K_DIM];          // 32 MB  [b][k] tf32
__device__ float g_wt[(size_t)N_ALL * K_DIM];          // 32 MB  [gate*1024+n][k] tf32
__device__ float g_z [(size_t)B_DIM * N_ALL];          // 64 MB  [b][gate*1024+n]

__device__ __forceinline__ float to_tf32(float x) {
    uint32_t u;
    asm("cvt.rna.tf32.f32 %0, %1;" : "=r"(u) : "f"(x));
    return __uint_as_float(u);
}

__device__ __forceinline__ uint32_t swz(uint32_t off) {   // byte-offset XOR swizzle
    return off ^ ((off >> 3) & 0x70);
}

__device__ __forceinline__ void cp16(uint32_t dst_smem, const void* src) {
    asm volatile("cp.async.cg.shared.global [%0], [%1], 16;"
                 :: "r"(dst_smem), "l"(src));
}

__device__ __forceinline__ uint32_t smem_u32(const void* p) {
    uint32_t a;
    asm("{ .reg .u64 t; cvta.to.shared.u64 t, %1; cvt.u32.u64 %0, t; }"
        : "=r"(a) : "l"(p));
    return a;
}

__device__ __forceinline__ void mma_tf32(float* d, const uint32_t* a, const uint32_t* b) {
    asm volatile(
        "mma.sync.aligned.m16n8k8.row.col.f32.tf32.tf32.f32 "
        "{%0,%1,%2,%3}, {%4,%5,%6,%7}, {%8,%9}, {%0,%1,%2,%3};"
        : "+f"(d[0]), "+f"(d[1]), "+f"(d[2]), "+f"(d[3])
        : "r"(a[0]), "r"(a[1]), "r"(a[2]), "r"(a[3]), "r"(b[0]), "r"(b[1]));
}

// ---------------------------------------------------------------------------
// prep 1: g_hx[b][k] = rna_tf32( k<1024 ? x[b][k] : h[b][k-1024] )
// ---------------------------------------------------------------------------
__global__ void prep_hx(const float4* __restrict__ x, const float4* __restrict__ h) {
    int v = blockIdx.x * 256 + threadIdx.x;          // 2,097,152 float4s
    int b = v >> 9;                                   // 512 float4 per row
    int kk = v & 511;
    float4 t = (kk < 256) ? x[(size_t)b * 256 + kk]
                          : h[(size_t)b * 256 + (kk - 256)];
    t.x = to_tf32(t.x); t.y = to_tf32(t.y); t.z = to_tf32(t.z); t.w = to_tf32(t.w);
    reinterpret_cast<float4*>(g_hx)[v] = t;
}

// ---------------------------------------------------------------------------
// prep 2: g_wt[g*1024+n][k] = rna_tf32( W_g[k][n] )   (tiled transpose)
// ---------------------------------------------------------------------------
__global__ void prep_wt(const float* __restrict__ Wf, const float* __restrict__ Wi,
                        const float* __restrict__ Ws, const float* __restrict__ Wp) {
    __shared__ float tile[32][33];
    int z = blockIdx.z;
    const float* W = (z == 0) ? Wf : (z == 1) ? Wi : (z == 2) ? Ws : Wp;
    int n0 = blockIdx.x * 32, k0 = blockIdx.y * 32;
    int tx = threadIdx.x, ty = threadIdx.y;
    #pragma unroll
    for (int r = ty; r < 32; r += 8)
        tile[r][tx] = to_tf32(W[(size_t)(k0 + r) * H_DIM + n0 + tx]);
    __syncthreads();
    #pragma unroll
    for (int r = ty; r < 32; r += 8)
        g_wt[((size_t)z * H_DIM + n0 + r) * K_DIM + k0 + tx] = tile[tx][r];
}

// ---------------------------------------------------------------------------
// GEMM: g_z[b][ng] = sum_k g_hx[b][k] * g_wt[ng][k]
//   CTA tile 128x128, BK=32, 4 cp.async stages, 256 threads.
//   Warp grid 2(m) x 4(n): warp tile 64x32. m16n8k8 tf32.
// SMEM per stage: A 16KB + B 16KB = 32KB; 4 stages = 128KB dynamic.
// ---------------------------------------------------------------------------
#define BK 32
#define STAGES 4
#define STAGE_FLOATS 8192            // 32KB / 4
#define B_OFF 4096                   // floats

__global__ void __launch_bounds__(256, 1)
gemm_tf32() {
    extern __shared__ float smem[];
    const uint32_t sbase = smem_u32(smem);
    const int tid = threadIdx.x;
    const int wid = tid >> 5, lane = tid & 31;
    const int wm = wid & 1;          // 0..1
    const int wn = wid >> 1;         // 0..3
    const int qr = lane >> 2, qc = lane & 3;
    const int m0 = blockIdx.y * 128;
    const int n0 = blockIdx.x * 128;

    const float* Abase = g_hx + (size_t)m0 * K_DIM;
    const float* Bbase = g_wt + (size_t)n0 * K_DIM;

    // cp.async granule assignment: 4 granules (16B) per thread per tile
    uint32_t dsw[4];
    uint32_t srcoff[4];
    #pragma unroll
    for (int j = 0; j < 4; j++) {
        int g = tid + 256 * j;       // 0..1023
        int row = g >> 3;            // 0..127
        int gc = g & 7;              // 16B granule in 128B row
        dsw[j] = swz((uint32_t)(row * 128 + gc * 16));
        srcoff[j] = (uint32_t)(row * K_DIM + gc * 4);
    }

    auto load_stage = [&](int s, int kt) {
        const uint32_t st = sbase + (uint32_t)s * (STAGE_FLOATS * 4);
        const float* ak = Abase + kt * BK;
        const float* bk = Bbase + kt * BK;
        #pragma unroll
        for (int j = 0; j < 4; j++) {
            cp16(st + dsw[j], ak + srcoff[j]);
            cp16(st + B_OFF * 4 + dsw[j], bk + srcoff[j]);
        }
        asm volatile("cp.async.commit_group;" ::: "memory");
    };

    // prologue
    load_stage(0, 0);
    load_stage(1, 1);
    load_stage(2, 2);

    float acc[4][4][4];
    #pragma unroll
    for (int i = 0; i < 4; i++)
        #pragma unroll
        for (int j = 0; j < 4; j++)
            #pragma unroll
            for (int v = 0; v < 4; v++) acc[i][j][v] = 0.0f;

    const uint32_t* S = reinterpret_cast<const uint32_t*>(smem);

    const int KT = K_DIM / BK;       // 64
    for (int kt = 0; kt < KT; kt++) {
        asm volatile("cp.async.wait_group 2;" ::: "memory");
        __syncthreads();

        const int s = kt & (STAGES - 1);
        const uint32_t abase_f = (uint32_t)s * STAGE_FLOATS;       // float index
        const uint32_t bbase_f = abase_f + B_OFF;

        #pragma unroll
        for (int kk = 0; kk < BK; kk += 8) {
            uint32_t afr[4][4], bfr[4][2];
            #pragma unroll
            for (int mt = 0; mt < 4; mt++) {
                int r = wm * 64 + mt * 16 + qr;
                afr[mt][0] = S[abase_f + (swz((uint32_t)(r * 128 + (kk + qc) * 4)) >> 2)];
                afr[mt][1] = S[abase_f + (swz((uint32_t)((r + 8) * 128 + (kk + qc) * 4)) >> 2)];
                afr[mt][2] = S[abase_f + (swz((uint32_t)(r * 128 + (kk + qc + 4) * 4)) >> 2)];
                afr[mt][3] = S[abase_f + (swz((uint32_t)((r + 8) * 128 + (kk + qc + 4) * 4)) >> 2)];
            }
            #pragma unroll
            for (int nt = 0; nt < 4; nt++) {
                int n = wn * 32 + nt * 8 + qr;
                bfr[nt][0] = S[bbase_f + (swz((uint32_t)(n * 128 + (kk + qc) * 4)) >> 2)];
                bfr[nt][1] = S[bbase_f + (swz((uint32_t)(n * 128 + (kk + qc + 4) * 4)) >> 2)];
            }
            #pragma unroll
            for (int mt = 0; mt < 4; mt++)
                #pragma unroll
                for (int nt = 0; nt < 4; nt++)
                    mma_tf32(acc[mt][nt], afr[mt], bfr[nt]);
        }

        if (kt + STAGES - 1 < KT) {
            load_stage((kt + STAGES - 1) & (STAGES - 1), kt + STAGES - 1);
        } else {
            asm volatile("cp.async.commit_group;" ::: "memory");
        }
    }

    // store accumulators to z
    #pragma unroll
    for (int mt = 0; mt < 4; mt++) {
        #pragma unroll
        for (int nt = 0; nt < 4; nt++) {
            int r = m0 + wm * 64 + mt * 16 + qr;
            int cg = n0 + wn * 32 + nt * 8 + qc * 2;
            float2* p0 = reinterpret_cast<float2*>(g_z + (size_t)r * N_ALL + cg);
            float2* p1 = reinterpret_cast<float2*>(g_z + (size_t)(r + 8) * N_ALL + cg);
            *p0 = make_float2(acc[mt][nt][0], acc[mt][nt][1]);
            *p1 = make_float2(acc[mt][nt][2], acc[mt][nt][3]);
        }
    }
}

// ---------------------------------------------------------------------------
// epilogue: h_new = tanh(c*sigm(zf+bf) + sigm(zi+bi)*tanh(zp+bp)) * sigm(zs+bs)
// ---------------------------------------------------------------------------
__global__ void epilogue(const float* __restrict__ c,
                         const float* __restrict__ bfo, const float* __restrict__ big,
                         const float* __restrict__ bse, const float* __restrict__ bpr,
                         float* __restrict__ out) {
    int idx = blockIdx.x * 256 + threadIdx.x;        // 0 .. 4096*256-1
    int b = idx >> 8;
    int n = (idx & 255) * 4;

    const float* zrow = g_z + (size_t)b * N_ALL;
    float4 zf = *reinterpret_cast<const float4*>(zrow + 0 * H_DIM + n);
    float4 zi = *reinterpret_cast<const float4*>(zrow + 1 * H_DIM + n);
    float4 zs = *reinterpret_cast<const float4*>(zrow + 2 * H_DIM + n);
    float4 zp = *reinterpret_cast<const float4*>(zrow + 3 * H_DIM + n);
    float4 cc = *reinterpret_cast<const float4*>(c + (size_t)b * H_DIM + n);
    float4 Bf = *reinterpret_cast<const float4*>(bfo + n);
    float4 Bi = *reinterpret_cast<const float4*>(big + n);
    float4 Bs = *reinterpret_cast<const float4*>(bse + n);
    float4 Bp = *reinterpret_cast<const float4*>(bpr + n);

    float rf[4] = {zf.x + Bf.x, zf.y + Bf.y, zf.z + Bf.z, zf.w + Bf.w};
    float ri[4] = {zi.x + Bi.x, zi.y + Bi.y, zi.z + Bi.z, zi.w + Bi.w};
    float rs[4] = {zs.x + Bs.x, zs.y + Bs.y, zs.z + Bs.z, zs.w + Bs.w};
    float rp[4] = {zp.x + Bp.x, zp.y + Bp.y, zp.z + Bp.z, zp.w + Bp.w};
    float ca[4] = {cc.x, cc.y, cc.z, cc.w};
    float res[4];
    #pragma unroll
    for (int j = 0; j < 4; j++) {
        float f  = 1.0f / (1.0f + __expf(-rf[j]));
        float ig = 1.0f / (1.0f + __expf(-ri[j]));
        float sl = 1.0f / (1.0f + __expf(-rs[j]));
        float pr = 1.0f - 2.0f / (1.0f + __expf(2.0f * rp[j]));
        float cn = ca[j] * f + ig * pr;
        float th = 1.0f - 2.0f / (1.0f + __expf(2.0f * cn));
        res[j] = th * sl;
    }
    *reinterpret_cast<float4*>(out + (size_t)b * H_DIM + n) =
        make_float4(res[0], res[1], res[2], res[3]);
}

// ---------------------------------------------------------------------------
// launch
// ---------------------------------------------------------------------------
extern "C" void kernel_launch(void* const* d_in, const int* in_sizes, int n_in,
                              void* d_out, int out_size) {
    const float* x  = (const float*)d_in[0];
    const float* h  = (const float*)d_in[1];
    const float* c  = (const float*)d_in[2];
    const float* Wf = (const float*)d_in[3];
    const float* bf = (const float*)d_in[4];
    const float* Wi = (const float*)d_in[5];
    const float* bi = (const float*)d_in[6];
    const float* Ws = (const float*)d_in[7];
    const float* bs = (const float*)d_in[8];
    const float* Wp = (const float*)d_in[9];
    const float* bp = (const float*)d_in[10];
    float* out = (float*)d_out;

    prep_hx<<<8192, 256>>>((const float4*)x, (const float4*)h);
    prep_wt<<<dim3(32, 64, 4), dim3(32, 8)>>>(Wf, Wi, Ws, Wp);

    cudaFuncSetAttribute(gemm_tf32, cudaFuncAttributeMaxDynamicSharedMemorySize,
                         STAGES * STAGE_FLOATS * 4);
    gemm_tf32<<<dim3(32, 32), 256, STAGES * STAGE_FLOATS * 4>>>();

    epilogue<<<4096, 256>>>(c, bf, bi, bs, bp, out);
}

// round 5
// speedup vs baseline: 1.0595x; 1.0595x over previous
#include <cuda_runtime.h>
#include <cuda_bf16.h>
#include <cstdint>

// ---------------------------------------------------------------------------
// LSTM cell: h_new = tanh(c*sigm(zf) + sigm(zi)*tanh(zp)) * sigm(zs)
// z_g = [x,h] @ W_g + b_g     B=4096, IN=H=1024, K=2048
//
// Harness PTX target is compute_100 (no 'a') => tcgen05 unavailable.
// mma.sync.m16n8k8.tf32 with rna-prerounded operands, cp.async 4-stage
// pipeline, XOR-swizzled smem, ldmatrix.x4 fragment loads.
// ---------------------------------------------------------------------------

#define B_DIM 4096
#define H_DIM 1024
#define K_DIM 2048
#define N_ALL 4096          // 4 gates x 1024

__device__ float g_hx[(size_t)B_DIM * K_DIM];          // 32 MB  [b][k] tf32
__device__ float g_wt[(size_t)N_ALL * K_DIM];          // 32 MB  [gate*1024+n][k] tf32
__device__ float g_z [(size_t)B_DIM * N_ALL];          // 64 MB  [b][gate*1024+n]

__device__ __forceinline__ float to_tf32(float x) {
    uint32_t u;
    asm("cvt.rna.tf32.f32 %0, %1;" : "=r"(u) : "f"(x));
    return __uint_as_float(u);
}

__device__ __forceinline__ uint32_t swz(uint32_t off) {   // byte-offset XOR swizzle
    return off ^ ((off >> 3) & 0x70);
}

__device__ __forceinline__ void cp16(uint32_t dst_smem, const void* src) {
    asm volatile("cp.async.cg.shared.global [%0], [%1], 16;"
                 :: "r"(dst_smem), "l"(src));
}

__device__ __forceinline__ uint32_t smem_u32(const void* p) {
    uint32_t a;
    asm("{ .reg .u64 t; cvta.to.shared.u64 t, %1; cvt.u32.u64 %0, t; }"
        : "=r"(a) : "l"(p));
    return a;
}

__device__ __forceinline__ void mma_tf32(float* d, const uint32_t* a, const uint32_t* b) {
    asm volatile(
        "mma.sync.aligned.m16n8k8.row.col.f32.tf32.tf32.f32 "
        "{%0,%1,%2,%3}, {%4,%5,%6,%7}, {%8,%9}, {%0,%1,%2,%3};"
        : "+f"(d[0]), "+f"(d[1]), "+f"(d[2]), "+f"(d[3])
        : "r"(a[0]), "r"(a[1]), "r"(a[2]), "r"(a[3]), "r"(b[0]), "r"(b[1]));
}

__device__ __forceinline__ void ldsm_x4(uint32_t* r, uint32_t addr) {
    asm volatile(
        "ldmatrix.sync.aligned.m8n8.x4.shared.b16 {%0,%1,%2,%3}, [%4];"
        : "=r"(r[0]), "=r"(r[1]), "=r"(r[2]), "=r"(r[3]) : "r"(addr));
}

// ---------------------------------------------------------------------------
// prep 1: g_hx[b][k] = rna_tf32( k<1024 ? x[b][k] : h[b][k-1024] )
// ---------------------------------------------------------------------------
__global__ void prep_hx(const float4* __restrict__ x, const float4* __restrict__ h) {
    int v = blockIdx.x * 256 + threadIdx.x;          // 2,097,152 float4s
    int b = v >> 9;                                   // 512 float4 per row
    int kk = v & 511;
    float4 t = (kk < 256) ? x[(size_t)b * 256 + kk]
                          : h[(size_t)b * 256 + (kk - 256)];
    t.x = to_tf32(t.x); t.y = to_tf32(t.y); t.z = to_tf32(t.z); t.w = to_tf32(t.w);
    reinterpret_cast<float4*>(g_hx)[v] = t;
}

// ---------------------------------------------------------------------------
// prep 2: g_wt[g*1024+n][k] = rna_tf32( W_g[k][n] )   (tiled transpose)
// ---------------------------------------------------------------------------
__global__ void prep_wt(const float* __restrict__ Wf, const float* __restrict__ Wi,
                        const float* __restrict__ Ws, const float* __restrict__ Wp) {
    __shared__ float tile[32][33];
    int z = blockIdx.z;
    const float* W = (z == 0) ? Wf : (z == 1) ? Wi : (z == 2) ? Ws : Wp;
    int n0 = blockIdx.x * 32, k0 = blockIdx.y * 32;
    int tx = threadIdx.x, ty = threadIdx.y;
    #pragma unroll
    for (int r = ty; r < 32; r += 8)
        tile[r][tx] = to_tf32(W[(size_t)(k0 + r) * H_DIM + n0 + tx]);
    __syncthreads();
    #pragma unroll
    for (int r = ty; r < 32; r += 8)
        g_wt[((size_t)z * H_DIM + n0 + r) * K_DIM + k0 + tx] = tile[tx][r];
}

// ---------------------------------------------------------------------------
// GEMM: g_z[b][ng] = sum_k g_hx[b][k] * g_wt[ng][k]
//   CTA 128x128, BK=32, 4 cp.async stages, 256 threads,
//   warp grid 2(m) x 4(n), warp tile 64x32, ldmatrix.x4 fragment loads.
// ---------------------------------------------------------------------------
#define BK 32
#define STAGES 4
#define STAGE_FLOATS 8192            // 32KB / 4
#define B_OFF 4096                   // floats

__global__ void __launch_bounds__(256, 1)
gemm_tf32() {
    extern __shared__ float smem[];
    const uint32_t sbase = smem_u32(smem);
    const int tid = threadIdx.x;
    const int wid = tid >> 5, lane = tid & 31;
    const int wm = wid & 1;          // 0..1
    const int wn = wid >> 1;         // 0..3
    const int qr = lane >> 2, qc = lane & 3;
    const int m0 = blockIdx.y * 128;
    const int n0 = blockIdx.x * 128;

    const float* Abase = g_hx + (size_t)m0 * K_DIM;
    const float* Bbase = g_wt + (size_t)n0 * K_DIM;

    // cp.async granule assignment: 4 granules (16B) per thread per tile
    uint32_t dsw[4];
    uint32_t srcoff[4];
    #pragma unroll
    for (int j = 0; j < 4; j++) {
        int g = tid + 256 * j;       // 0..1023
        int row = g >> 3;            // 0..127
        int gc = g & 7;              // 16B granule in 128B row
        dsw[j] = swz((uint32_t)(row * 128 + gc * 16));
        srcoff[j] = (uint32_t)(row * K_DIM + gc * 4);
    }

    auto load_stage = [&](int s, int kt) {
        const uint32_t st = sbase + (uint32_t)s * (STAGE_FLOATS * 4);
        const float* ak = Abase + kt * BK;
        const float* bk = Bbase + kt * BK;
        #pragma unroll
        for (int j = 0; j < 4; j++) {
            cp16(st + dsw[j], ak + srcoff[j]);
            cp16(st + B_OFF * 4 + dsw[j], bk + srcoff[j]);
        }
        asm volatile("cp.async.commit_group;" ::: "memory");
    };

    // prologue
    load_stage(0, 0);
    load_stage(1, 1);
    load_stage(2, 2);

    float acc[4][4][4];
    #pragma unroll
    for (int i = 0; i < 4; i++)
        #pragma unroll
        for (int j = 0; j < 4; j++)
            #pragma unroll
            for (int v = 0; v < 4; v++) acc[i][j][v] = 0.0f;

    // ldmatrix lane-invariant address components (byte offsets inside a tile)
    // A (per mt): matrices {rows 0-7, rows 8-15} x {k, k+4}
    //   lane l: row = wm*64 + (l&15) (+ mt*16 rows), colbyte = (l&16) ? 16 : 0
    const uint32_t a_row = (uint32_t)(wm * 64 + (lane & 15));
    const uint32_t a_col = (lane & 16) ? 16u : 0u;
    const uint32_t a_off0 = a_row * 128 + a_col;
    // B t0 (nt0,nt1): lane l: n = wn*32 + ((l&16)?8:0) + (l&7), colbyte = (l&8)?16:0
    //   t1 (nt2,nt3) adds 16 n-rows = 2048 bytes
    const uint32_t b_n = (uint32_t)(wn * 32 + ((lane & 16) ? 8 : 0) + (lane & 7));
    const uint32_t b_col = (lane & 8) ? 16u : 0u;
    const uint32_t b_off0 = b_n * 128 + b_col;

    const int KT = K_DIM / BK;       // 64
    for (int kt = 0; kt < KT; kt++) {
        asm volatile("cp.async.wait_group 2;" ::: "memory");
        __syncthreads();

        const int s = kt & (STAGES - 1);
        const uint32_t stA = sbase + (uint32_t)s * (STAGE_FLOATS * 4);
        const uint32_t stB = stA + B_OFF * 4;

        #pragma unroll
        for (int kk = 0; kk < BK; kk += 8) {
            const uint32_t kb = (uint32_t)kk * 4;
            uint32_t afr[4][4], bfr[4][2];
            #pragma unroll
            for (int mt = 0; mt < 4; mt++)
                ldsm_x4(afr[mt], stA + swz(a_off0 + (uint32_t)mt * 2048 + kb));
            {
                uint32_t t0[4], t1[4];
                ldsm_x4(t0, stB + swz(b_off0 + kb));
                ldsm_x4(t1, stB + swz(b_off0 + 2048 + kb));   // +16 n-rows (FIXED)
                bfr[0][0] = t0[0]; bfr[0][1] = t0[1];
                bfr[1][0] = t0[2]; bfr[1][1] = t0[3];
                bfr[2][0] = t1[0]; bfr[2][1] = t1[1];
                bfr[3][0] = t1[2]; bfr[3][1] = t1[3];
            }
            #pragma unroll
            for (int mt = 0; mt < 4; mt++)
                #pragma unroll
                for (int nt = 0; nt < 4; nt++)
                    mma_tf32(acc[mt][nt], afr[mt], bfr[nt]);
        }

        if (kt + STAGES - 1 < KT) {
            load_stage((kt + STAGES - 1) & (STAGES - 1), kt + STAGES - 1);
        } else {
            asm volatile("cp.async.commit_group;" ::: "memory");
        }
    }

    // store accumulators to z
    #pragma unroll
    for (int mt = 0; mt < 4; mt++) {
        #pragma unroll
        for (int nt = 0; nt < 4; nt++) {
            int r = m0 + wm * 64 + mt * 16 + qr;
            int cg = n0 + wn * 32 + nt * 8 + qc * 2;
            float2* p0 = reinterpret_cast<float2*>(g_z + (size_t)r * N_ALL + cg);
            float2* p1 = reinterpret_cast<float2*>(g_z + (size_t)(r + 8) * N_ALL + cg);
            *p0 = make_float2(acc[mt][nt][0], acc[mt][nt][1]);
            *p1 = make_float2(acc[mt][nt][2], acc[mt][nt][3]);
        }
    }
}

// ---------------------------------------------------------------------------
// epilogue: h_new = tanh(c*sigm(zf+bf) + sigm(zi+bi)*tanh(zp+bp)) * sigm(zs+bs)
// ---------------------------------------------------------------------------
__global__ void epilogue(const float* __restrict__ c,
                         const float* __restrict__ bfo, const float* __restrict__ big,
                         const float* __restrict__ bse, const float* __restrict__ bpr,
                         float* __restrict__ out) {
    int idx = blockIdx.x * 256 + threadIdx.x;        // 0 .. 4096*256-1
    int b = idx >> 8;
    int n = (idx & 255) * 4;

    const float* zrow = g_z + (size_t)b * N_ALL;
    float4 zf = *reinterpret_cast<const float4*>(zrow + 0 * H_DIM + n);
    float4 zi = *reinterpret_cast<const float4*>(zrow + 1 * H_DIM + n);
    float4 zs = *reinterpret_cast<const float4*>(zrow + 2 * H_DIM + n);
    float4 zp = *reinterpret_cast<const float4*>(zrow + 3 * H_DIM + n);
    float4 cc = *reinterpret_cast<const float4*>(c + (size_t)b * H_DIM + n);
    float4 Bf = *reinterpret_cast<const float4*>(bfo + n);
    float4 Bi = *reinterpret_cast<const float4*>(big + n);
    float4 Bs = *reinterpret_cast<const float4*>(bse + n);
    float4 Bp = *reinterpret_cast<const float4*>(bpr + n);

    float rf[4] = {zf.x + Bf.x, zf.y + Bf.y, zf.z + Bf.z, zf.w + Bf.w};
    float ri[4] = {zi.x + Bi.x, zi.y + Bi.y, zi.z + Bi.z, zi.w + Bi.w};
    float rs[4] = {zs.x + Bs.x, zs.y + Bs.y, zs.z + Bs.z, zs.w + Bs.w};
    float rp[4] = {zp.x + Bp.x, zp.y + Bp.y, zp.z + Bp.z, zp.w + Bp.w};
    float ca[4] = {cc.x, cc.y, cc.z, cc.w};
    float res[4];
    #pragma unroll
    for (int j = 0; j < 4; j++) {
        float f  = 1.0f / (1.0f + __expf(-rf[j]));
        float ig = 1.0f / (1.0f + __expf(-ri[j]));
        float sl = 1.0f / (1.0f + __expf(-rs[j]));
        float pr = 1.0f - 2.0f / (1.0f + __expf(2.0f * rp[j]));
        float cn = ca[j] * f + ig * pr;
        float th = 1.0f - 2.0f / (1.0f + __expf(2.0f * cn));
        res[j] = th * sl;
    }
    *reinterpret_cast<float4*>(out + (size_t)b * H_DIM + n) =
        make_float4(res[0], res[1], res[2], res[3]);
}

// ---------------------------------------------------------------------------
// launch
// ---------------------------------------------------------------------------
extern "C" void kernel_launch(void* const* d_in, const int* in_sizes, int n_in,
                              void* d_out, int out_size) {
    const float* x  = (const float*)d_in[0];
    const float* h  = (const float*)d_in[1];
    const float* c  = (const float*)d_in[2];
    const float* Wf = (const float*)d_in[3];
    const float* bf = (const float*)d_in[4];
    const float* Wi = (const float*)d_in[5];
    const float* bi = (const float*)d_in[6];
    const float* Ws = (const float*)d_in[7];
    const float* bs = (const float*)d_in[8];
    const float* Wp = (const float*)d_in[9];
    const float* bp = (const float*)d_in[10];
    float* out = (float*)d_out;

    prep_hx<<<8192, 256>>>((const float4*)x, (const float4*)h);
    prep_wt<<<dim3(32, 64, 4), dim3(32, 8)>>>(Wf, Wi, Ws, Wp);

    cudaFuncSetAttribute(gemm_tf32, cudaFuncAttributeMaxDynamicSharedMemorySize,
                         STAGES * STAGE_FLOATS * 4);
    gemm_tf32<<<dim3(32, 32), 256, STAGES * STAGE_FLOATS * 4>>>();

    epilogue<<<4096, 256>>>(c, bf, bi, bs, bp, out);
}